// round 16
// baseline (speedup 1.0000x reference)
#include <cuda_runtime.h>
#include <cuda_fp16.h>
#include <cstdint>

#define BB 4
#define NN 512
#define HH 64
#define DIRD 64
#define MLPD 128
#define LDH 72                       // 64 data halves + 8 constant channels

// Scratch (allocation-free rule: __device__ globals)
__device__ __align__(16) __half g_KhX[BB*NN*LDH];   // K fp16 + baked const channels
__device__ __align__(16) __half g_Qh[BB*NN*HH];
__device__ __align__(16) __half g_W1Th[MLPD*HH];    // W1[:64] transposed, fp16
__device__ float g_V[BB*NN*HH];
__device__ float g_E[4*MLPD];
__device__ float g_c0[MLPD];
__device__ float g_S[BB*NN*NN];   // raw scores, 4 MB
__device__ int   g_flag[BB*NN/8]; // per 8-row group publish counters

// ---------------------------------------------------------------------------
__device__ __forceinline__ uint32_t smem_u32(const void* p) {
    uint32_t a;
    asm("{ .reg .u64 t; cvta.to.shared.u64 t, %1; cvt.u32.u64 %0, t; }" : "=r"(a) : "l"(p));
    return a;
}
__device__ __forceinline__ void mma_f16(float d[4], const uint32_t a[4], const uint32_t b[2]) {
    asm volatile("mma.sync.aligned.m16n8k16.row.col.f32.f16.f16.f32 "
                 "{%0,%1,%2,%3}, {%4,%5,%6,%7}, {%8,%9}, {%0,%1,%2,%3};"
                 : "+f"(d[0]), "+f"(d[1]), "+f"(d[2]), "+f"(d[3])
                 : "r"(a[0]), "r"(a[1]), "r"(a[2]), "r"(a[3]),
                   "r"(b[0]), "r"(b[1]));
}
__device__ __forceinline__ void mma_f16_k8(float d[4], uint32_t a0, uint32_t a1, uint32_t b0) {
    asm volatile("mma.sync.aligned.m16n8k8.row.col.f32.f16.f16.f32 "
                 "{%0,%1,%2,%3}, {%4,%5}, {%6}, {%0,%1,%2,%3};"
                 : "+f"(d[0]), "+f"(d[1]), "+f"(d[2]), "+f"(d[3])
                 : "r"(a0), "r"(a1), "r"(b0));
}
__device__ __forceinline__ void ldsm_x4(uint32_t& r0, uint32_t& r1, uint32_t& r2, uint32_t& r3,
                                        uint32_t addr) {
    asm volatile("ldmatrix.sync.aligned.m8n8.x4.shared.b16 {%0,%1,%2,%3}, [%4];"
                 : "=r"(r0), "=r"(r1), "=r"(r2), "=r"(r3) : "r"(addr));
}
#define CP_A16(dst, src) \
    asm volatile("cp.async.cg.shared.global [%0], [%1], 16;" :: "r"(dst), "l"(src) : "memory")
#define CP_COMMIT() asm volatile("cp.async.commit_group;" ::: "memory")
#define CP_WAIT(n)  asm volatile("cp.async.wait_group %0;" :: "n"(n) : "memory")

__device__ __forceinline__ void h_split(float x, __half& hi, __half& lo) {
    hi = __float2half_rn(x);
    lo = __float2half_rn(x - __half2float(hi));
}
__device__ __forceinline__ uint32_t hmul2(uint32_t a, uint32_t b) {
    uint32_t r;
    asm("mul.rn.f16x2 %0, %1, %2;" : "=r"(r) : "r"(a), "r"(b));
    return r;
}

// ---------------------------------------------------------------------------
// Kernel 1: Q/K/V projections (Q,K fp16; K row gets baked const channels).
// Block NB: dirfold + flag reset.  Block NB+1: W1T fp16 transpose.
// ---------------------------------------------------------------------------
#define QKV_ROWS 16
#define QKV_NB   (BB*NN/QKV_ROWS)
#define QKV_SMEM (3*HH*HH*4 + QKV_ROWS*HH*4)
__global__ void __launch_bounds__(512, 2)
qkv_kernel(const float* __restrict__ feat, const float* __restrict__ loc,
           const float* __restrict__ Wq, const float* __restrict__ bq,
           const float* __restrict__ Wk, const float* __restrict__ bk,
           const float* __restrict__ Wv, const float* __restrict__ bv,
           const float* __restrict__ Wd, const float* __restrict__ bd,
           const float* __restrict__ W1, const float* __restrict__ b1) {
    const int t = threadIdx.x;

    if (blockIdx.x == QKV_NB) {
        // ---- flag reset (graph-replay determinism)
        if (t >= MLPD && t < MLPD + BB*NN/8) g_flag[t - MLPD] = 0;
        // ---- dirfold: E = Wd @ W1[64:], c0 = b1 + bd @ W1[64:]
        if (t < MLPD) {
            int m = t;
            float e0 = 0.f, e1 = 0.f, e2 = 0.f, e3 = 0.f, c = b1[m];
#pragma unroll 16
            for (int d = 0; d < DIRD; ++d) {
                float w = W1[(HH + d)*MLPD + m];
                e0 = fmaf(Wd[0*DIRD + d], w, e0);
                e1 = fmaf(Wd[1*DIRD + d], w, e1);
                e2 = fmaf(Wd[2*DIRD + d], w, e2);
                e3 = fmaf(Wd[3*DIRD + d], w, e3);
                c  = fmaf(bd[d],          w, c);
            }
            g_E[0*MLPD + m] = e0;
            g_E[1*MLPD + m] = e1;
            g_E[2*MLPD + m] = e2;
            g_E[3*MLPD + m] = e3;
            g_c0[m] = c;
        }
        return;
    }
    if (blockIdx.x == QKV_NB + 1) {
        // ---- W1T fp16: g_W1Th[m*64 + h] = f16(W1[h*128 + m])
#pragma unroll
        for (int k = 0; k < 16; ++k) {
            int idx = t + k*512;
            int m = idx >> 6, h = idx & 63;
            g_W1Th[idx] = __float2half_rn(W1[h*MLPD + m]);
        }
        return;
    }

    extern __shared__ float qs[];
    float* sWq = qs;
    float* sWk = qs + HH*HH;
    float* sWv = qs + 2*HH*HH;
    float* sF  = qs + 3*HH*HH;
    const int row0 = blockIdx.x * QKV_ROWS;

    {
        const float4* wq4 = (const float4*)Wq;
        const float4* wk4 = (const float4*)Wk;
        const float4* wv4 = (const float4*)Wv;
        float4* dq = (float4*)sWq;
        float4* dk = (float4*)sWk;
        float4* dv = (float4*)sWv;
#pragma unroll
        for (int k = 0; k < 2; ++k) {
            int idx = t + k*512;
            dq[idx] = wq4[idx];
            dk[idx] = wk4[idx];
            dv[idx] = wv4[idx];
        }
        const float4* f4 = (const float4*)&feat[row0*HH];
        if (t < QKV_ROWS*HH/4) ((float4*)sF)[t] = f4[t];
    }
    __syncthreads();

    const int h = t & 63;
    const int rg = t >> 6;               // 8 groups x 2 rows
    float aq[2], ak[2], av[2];
    float vbq = bq[h], vbk = bk[h], vbv = bv[h];
#pragma unroll
    for (int r = 0; r < 2; ++r) { aq[r] = vbq; ak[r] = vbk; av[r] = vbv; }
#pragma unroll 8
    for (int k = 0; k < HH; ++k) {
        float wq = sWq[k*HH + h], wk = sWk[k*HH + h], wv = sWv[k*HH + h];
#pragma unroll
        for (int r = 0; r < 2; ++r) {
            float f = sF[(rg*2 + r)*HH + k];
            aq[r] = fmaf(f, wq, aq[r]);
            ak[r] = fmaf(f, wk, ak[r]);
            av[r] = fmaf(f, wv, av[r]);
        }
    }
#pragma unroll
    for (int r = 0; r < 2; ++r) {
        int row = row0 + rg*2 + r;
        g_Qh[row*HH + h]   = __float2half_rn(aq[r]);
        g_KhX[row*LDH + h] = __float2half_rn(ak[r]);
        g_V[row*HH + h]    = av[r];
    }
    // baked A const channels (k = 64..71) for this block's rows
    if (t < QKV_ROWS) {
        int row = row0 + t;
        int j = row & (NN - 1);
        float2 l = *(const float2*)&loc[j*2];
        __half l0h, l0l, l1h, l1l;
        h_split(l.x, l0h, l0l);
        h_split(l.y, l1h, l1l);
        __half one = __float2half_rn(1.f);
        __half c[8] = {one, one, l0h, l0h, l0l, l1h, l1h, l1l};
        *(uint4*)&g_KhX[row*LDH + 64] = *(uint4*)c;
    }
}

// ---------------------------------------------------------------------------
// Kernel 2 (fused): blocks < 2048 -> scores for (b,i) + publish flag.
// blocks >= 2048 -> softmax + attn@V for one 8-row group (spin on flags).
// Mainloop: 32-row j-subtiles (mi=2), B fragments hoisted across subtiles.
// ---------------------------------------------------------------------------
#define SA_OFF   0                   // 512*72*2 = 73728
#define SB_OFF   73728               // 128*72*2 = 18432 -> 92160
#define SP_OFF   92160               // 4*512*4  = 8192  -> 100352
#define SW2_OFF  100352              // 128*4    = 512   -> 100864
#define SC_TOTAL 100864
#define IB 8
#define VT 64
#define NSCORE (BB*NN)

__global__ void __launch_bounds__(256, 2)
attn_fused_kernel(const float* __restrict__ wind, const float* __restrict__ loc,
                  const float* __restrict__ W2, float* __restrict__ out) {
    extern __shared__ __align__(16) char sm[];
    const int t    = threadIdx.x;
    const int wid  = t >> 5;
    const int lane = t & 31;
    const int blk  = blockIdx.x;

    if (blk >= NSCORE) {
        // =============== consumer: softmax + attn@V for one group ===========
        float* sS = (float*)sm;               // [IB][NN]
        float* sV = (float*)(sm + IB*NN*4);   // [2][VT][HH]
        const int grp = blk - NSCORE;         // 0..255
        const int b   = grp >> 6;
        const int i0  = (grp & 63) * IB;
        const int bN  = b * NN;
        const uint32_t svb = smem_u32(sV);

        // prefetch V tile 0 (V ready: qkv retired before this kernel)
        {
            const char* src = (const char*)&g_V[bN*HH];
#pragma unroll
            for (int k = 0; k < 4; ++k) {
                int idx = t + k*256;
                CP_A16(svb + idx*16, src + idx*16);
            }
            CP_COMMIT();
        }

        // spin until this group's 8 producer blocks have published
        if (t == 0) {
            int v;
            do {
                asm volatile("ld.acquire.gpu.s32 %0, [%1];"
                             : "=r"(v) : "l"(&g_flag[grp]) : "memory");
                if (v != IB) __nanosleep(128);
            } while (v != IB);
        }
        __syncthreads();
        __threadfence();

        // load 8 rows of raw scores
        {
            const float4* src = (const float4*)&g_S[((size_t)bN + i0) * NN];
            float4* dst = (float4*)sS;
#pragma unroll
            for (int k = 0; k < 4; ++k) dst[t + k*256] = src[t + k*256];
        }
        __syncthreads();

        // per-row softmax: warp wid owns row wid
        float inv;
        {
            float* r = &sS[wid*NN];
            float m = -1e30f;
#pragma unroll
            for (int c = 0; c < NN/32; ++c) m = fmaxf(m, r[c*32 + lane]);
#pragma unroll
            for (int o = 16; o > 0; o >>= 1) m = fmaxf(m, __shfl_xor_sync(0xffffffffu, m, o));
            float sum = 0.f;
#pragma unroll
            for (int c = 0; c < NN/32; ++c) {
                float e = __expf(r[c*32 + lane] - m);
                r[c*32 + lane] = e;
                sum += e;
            }
#pragma unroll
            for (int o = 16; o > 0; o >>= 1) sum += __shfl_xor_sync(0xffffffffu, sum, o);
            inv = 1.f / sum;
        }

        // AV over 8 V tiles (double-buffered)
        const int h4 = lane & 15;
        const int jh = lane >> 4;
        float4 acc = make_float4(0.f, 0.f, 0.f, 0.f);

#pragma unroll
        for (int jt = 0; jt < NN/VT; ++jt) {
            if (jt + 1 < NN/VT) {
                const char* src = (const char*)&g_V[(bN + (jt + 1)*VT)*HH];
                uint32_t dstb = svb + ((jt + 1) & 1) * (VT*HH*4);
#pragma unroll
                for (int k = 0; k < 4; ++k) {
                    int idx = t + k*256;
                    CP_A16(dstb + idx*16, src + idx*16);
                }
                CP_COMMIT();
                CP_WAIT(1);
            } else {
                CP_WAIT(0);
            }
            __syncthreads();
            const float*  Prow = &sS[wid*NN + jt*VT + jh*32];
            const float4* V4   = (const float4*)&sV[(jt & 1)*VT*HH];
#pragma unroll 4
            for (int j = 0; j < 32; ++j) {
                float p = Prow[j];
                float4 v = V4[(jh*32 + j)*16 + h4];
                acc.x = fmaf(p, v.x, acc.x);
                acc.y = fmaf(p, v.y, acc.y);
                acc.z = fmaf(p, v.z, acc.z);
                acc.w = fmaf(p, v.w, acc.w);
            }
            __syncthreads();
        }

        acc.x += __shfl_xor_sync(0xffffffffu, acc.x, 16);
        acc.y += __shfl_xor_sync(0xffffffffu, acc.y, 16);
        acc.z += __shfl_xor_sync(0xffffffffu, acc.z, 16);
        acc.w += __shfl_xor_sync(0xffffffffu, acc.w, 16);
        if (jh == 0) {
            acc.x *= inv; acc.y *= inv; acc.z *= inv; acc.w *= inv;
            ((float4*)&out[(bN + i0 + wid)*HH])[h4] = acc;
        }
        return;
    }

    // =================== producer: scores for (b,i) ========================
    __half*  sA  = (__half*)(sm + SA_OFF);
    __half*  sB  = (__half*)(sm + SB_OFF);
    float*   sP  = (float*)(sm + SP_OFF);
    float*   sW2 = (float*)(sm + SW2_OFF);

    const int b    = blk >> 9;
    const int i    = blk & (NN - 1);
    const int bN   = b * NN;
    const uint32_t sAb = smem_u32(sA);
    const uint32_t sBb = smem_u32(sB);

    // 1. flat cp.async of the whole A tile (data + baked const channels)
    {
        const char* src = (const char*)&g_KhX[bN*LDH];
#pragma unroll
        for (int k = 0; k < 18; ++k) {
            uint32_t off = (uint32_t)(t + k*256) * 16;
            CP_A16(sAb + off, src + off);
        }
        CP_COMMIT();
    }

    // 2. per-i constant channels for B rows (k = 64..71) + W2
    if (t < MLPD) {
        float li0 = loc[i*2 + 0], li1 = loc[i*2 + 1];
        float w0  = wind[(bN + i)*2 + 0], w1v = wind[(bN + i)*2 + 1];
        float e0 = g_E[t], e1 = g_E[MLPD + t], e2 = g_E[2*MLPD + t], e3 = g_E[3*MLPD + t];
        float f  = g_c0[t] - li0*e0 - li1*e1 + w0*e2 + w1v*e3;
        __half fh, fl, e0h, e0l, e1h, e1l;
        h_split(f,  fh,  fl);
        h_split(e0, e0h, e0l);
        h_split(e1, e1h, e1l);
        __half c[8] = {fh, fl, e0h, e0l, e0h, e1h, e1l, e1h};
        *(uint4*)&sB[t*LDH + 64] = *(uint4*)c;
        sW2[t] = W2[t];
    }

    // 3. stage B data: sB[m][h] = W1Th[m][h] * Qh[i][h]  (fp16 x fp16)
    {
        const uint4* w4 = (const uint4*)g_W1Th;
        const uint4* q4 = (const uint4*)&g_Qh[(bN + i)*HH];
#pragma unroll
        for (int k = 0; k < 4; ++k) {
            int idx = t + k*256;
            int m = idx >> 3, oct = idx & 7;
            uint4 w = __ldg(&w4[idx]);
            uint4 q = __ldg(&q4[oct]);
            uint4 r;
            r.x = hmul2(w.x, q.x);
            r.y = hmul2(w.y, q.y);
            r.z = hmul2(w.z, q.z);
            r.w = hmul2(w.w, q.w);
            *(uint4*)&sB[m*LDH + oct*8] = r;
        }
    }
    CP_WAIT(0);
    __syncthreads();   // A + B fully staged

    const int wj  = wid >> 2;      // 0..1  (j half: 256 rows)
    const int wm  = wid & 3;       // 0..3  (m block of 32)
    const int g   = lane >> 2;
    const int tig = lane & 3;

    // hoisted B fragments: all 4 kc chunks (invariant across subtiles)
    uint32_t Bf[4][4][2];
    {
        uint32_t bAddr0, bAddr1;
        int idx4   = lane >> 3;
        int ni_off = idx4 >> 1;
        int koff   = (idx4 & 1) * 8;
        int n0 = wm*32 + 0*16 + ni_off*8 + (lane & 7);
        int n1 = wm*32 + 1*16 + ni_off*8 + (lane & 7);
        bAddr0 = sBb + (uint32_t)(n0*LDH + koff) * 2;
        bAddr1 = sBb + (uint32_t)(n1*LDH + koff) * 2;
#pragma unroll
        for (int kc = 0; kc < 4; ++kc) {
            const uint32_t kb = kc * 32;
            ldsm_x4(Bf[kc][0][0], Bf[kc][0][1], Bf[kc][1][0], Bf[kc][1][1], bAddr0 + kb);
            ldsm_x4(Bf[kc][2][0], Bf[kc][2][1], Bf[kc][3][0], Bf[kc][3][1], bAddr1 + kb);
        }
    }
    // hoisted B k8 fragments
    uint32_t B8[4];
    {
        int n = wm*32 + (lane >> 3)*8 + (lane & 7);
        ldsm_x4(B8[0], B8[1], B8[2], B8[3], sBb + (uint32_t)(n*LDH + 64) * 2);
    }
    // hoisted W2 registers
    float w2r[8];
#pragma unroll
    for (int ni = 0; ni < 4; ++ni) {
        int m0 = wm*32 + ni*8 + 2*tig;
        w2r[ni*2]     = sW2[m0];
        w2r[ni*2 + 1] = sW2[m0 + 1];
    }

    // per-lane A address components (subtile-invariant parts)
    const int aRowLoc  = lane & 15;          // k16: row within 16-row frag
    const int aKOff    = (lane >> 4) * 8;    // k16: k offset
    const int a8RowLoc = ((lane >> 4) & 1)*16 + (((lane >> 3) & 1))*8 + (lane & 7);
    // (idx = lane>>3: row = (idx>>1)*16 + (idx&1)*8 + (lane&7), covers 32 rows)

    // 4. compute: 8 subtiles of 32 j-rows per warp (mi=2)
#pragma unroll
    for (int tj = 0; tj < 8; ++tj) {
        const int rowb = wj*256 + tj*32;
        uint32_t aAddr[2];
#pragma unroll
        for (int mi = 0; mi < 2; ++mi) {
            int r0 = rowb + mi*16 + aRowLoc;
            aAddr[mi] = sAb + (uint32_t)(r0*LDH + aKOff) * 2;
        }
        uint32_t a8Addr = sAb + (uint32_t)((rowb + a8RowLoc)*LDH + 64) * 2;

        float d[2][4][4];
#pragma unroll
        for (int mi = 0; mi < 2; ++mi)
#pragma unroll
            for (int ni = 0; ni < 4; ++ni)
#pragma unroll
                for (int r = 0; r < 4; ++r) d[mi][ni][r] = 0.f;

        // constant-channel k8 MMAs
        {
            uint32_t A8[4];
            ldsm_x4(A8[0], A8[1], A8[2], A8[3], a8Addr);
#pragma unroll
            for (int mi = 0; mi < 2; ++mi)
#pragma unroll
                for (int ni = 0; ni < 4; ++ni)
                    mma_f16_k8(d[mi][ni], A8[mi*2], A8[mi*2 + 1], B8[ni]);
        }

#pragma unroll
        for (int kc = 0; kc < 4; ++kc) {
            const uint32_t kb = kc * 32;
            uint32_t Af[2][4];
#pragma unroll
            for (int mi = 0; mi < 2; ++mi)
                ldsm_x4(Af[mi][0], Af[mi][1], Af[mi][2], Af[mi][3], aAddr[mi] + kb);
#pragma unroll
            for (int mi = 0; mi < 2; ++mi)
#pragma unroll
                for (int ni = 0; ni < 4; ++ni)
                    mma_f16(d[mi][ni], Af[mi], Bf[kc][ni]);
        }

        // lean epilogue: relu . W2 only
#pragma unroll
        for (int mi = 0; mi < 2; ++mi) {
            int jl = rowb + mi*16 + g;
            float p0 = 0.f, p1 = 0.f;
#pragma unroll
            for (int ni = 0; ni < 4; ++ni) {
                p0 = fmaf(fmaxf(d[mi][ni][0], 0.f), w2r[ni*2],     p0);
                p0 = fmaf(fmaxf(d[mi][ni][1], 0.f), w2r[ni*2 + 1], p0);
                p1 = fmaf(fmaxf(d[mi][ni][2], 0.f), w2r[ni*2],     p1);
                p1 = fmaf(fmaxf(d[mi][ni][3], 0.f), w2r[ni*2 + 1], p1);
            }
            p0 += __shfl_xor_sync(0xffffffffu, p0, 1);
            p0 += __shfl_xor_sync(0xffffffffu, p0, 2);
            p1 += __shfl_xor_sync(0xffffffffu, p1, 1);
            p1 += __shfl_xor_sync(0xffffffffu, p1, 2);
            if (tig == 0) {
                sP[wm*NN + jl]     = p0;
                sP[wm*NN + jl + 8] = p1;
            }
        }
    }
    __syncthreads();

    // 5. combine partials, write raw scores, publish
#pragma unroll
    for (int rr = 0; rr < 2; ++rr) {
        int j = t + rr*256;
        float s = sP[j] + sP[NN + j] + sP[2*NN + j] + sP[3*NN + j];
        g_S[(size_t)blk*NN + j] = s;
    }
    __syncthreads();
    if (t == 0) {
        __threadfence();
        atomicAdd(&g_flag[blk >> 3], 1);
    }
}

// ---------------------------------------------------------------------------
extern "C" void kernel_launch(void* const* d_in, const int* in_sizes, int n_in,
                              void* d_out, int out_size) {
    const float* features = (const float*)d_in[0];
    const float* wind     = (const float*)d_in[1];
    const float* loc      = (const float*)d_in[2];
    const float* Wq       = (const float*)d_in[3];
    const float* bq       = (const float*)d_in[4];
    const float* Wk       = (const float*)d_in[5];
    const float* bk       = (const float*)d_in[6];
    const float* Wv       = (const float*)d_in[7];
    const float* bv       = (const float*)d_in[8];
    const float* Wd       = (const float*)d_in[9];
    const float* bd       = (const float*)d_in[10];
    const float* W1       = (const float*)d_in[11];
    const float* b1       = (const float*)d_in[12];
    const float* W2       = (const float*)d_in[13];
    // d_in[14] = b2: softmax-invariant -> dropped.
    (void)in_sizes; (void)n_in; (void)out_size;

    cudaFuncSetAttribute(qkv_kernel, cudaFuncAttributeMaxDynamicSharedMemorySize, QKV_SMEM);
    cudaFuncSetAttribute(attn_fused_kernel, cudaFuncAttributeMaxDynamicSharedMemorySize, SC_TOTAL);

    qkv_kernel<<<QKV_NB + 2, 512, QKV_SMEM>>>(features, loc, Wq, bq, Wk, bk, Wv, bv,
                                              Wd, bd, W1, b1);
    attn_fused_kernel<<<NSCORE + NSCORE/IB, 256, SC_TOTAL>>>(wind, loc, W2, (float*)d_out);
}

// round 17
// speedup vs baseline: 1.0204x; 1.0204x over previous
#include <cuda_runtime.h>
#include <cuda_fp16.h>
#include <cstdint>

#define BB 4
#define NN 512
#define HH 64
#define DIRD 64
#define MLPD 128
#define LDH 72                       // 64 data halves + 8 constant channels

// Scratch (allocation-free rule: __device__ globals)
__device__ __align__(16) __half g_KhX[BB*NN*LDH];   // K fp16 + baked const channels
__device__ __align__(16) __half g_Qh[BB*NN*HH];
__device__ __align__(16) __half g_W1Th[MLPD*HH];    // W1[:64] transposed, fp16
__device__ float g_V[BB*NN*HH];
__device__ float g_E[4*MLPD];
__device__ float g_c0[MLPD];
__device__ float g_S[BB*NN*NN];   // raw scores, 4 MB
__device__ int   g_flag[BB*NN/8]; // per 8-row group publish counters

// ---------------------------------------------------------------------------
__device__ __forceinline__ uint32_t smem_u32(const void* p) {
    uint32_t a;
    asm("{ .reg .u64 t; cvta.to.shared.u64 t, %1; cvt.u32.u64 %0, t; }" : "=r"(a) : "l"(p));
    return a;
}
__device__ __forceinline__ void mma_f16(float d[4], const uint32_t a[4], const uint32_t b[2]) {
    asm volatile("mma.sync.aligned.m16n8k16.row.col.f32.f16.f16.f32 "
                 "{%0,%1,%2,%3}, {%4,%5,%6,%7}, {%8,%9}, {%0,%1,%2,%3};"
                 : "+f"(d[0]), "+f"(d[1]), "+f"(d[2]), "+f"(d[3])
                 : "r"(a[0]), "r"(a[1]), "r"(a[2]), "r"(a[3]),
                   "r"(b[0]), "r"(b[1]));
}
__device__ __forceinline__ void mma_f16_k8(float d[4], uint32_t a0, uint32_t a1, uint32_t b0) {
    asm volatile("mma.sync.aligned.m16n8k8.row.col.f32.f16.f16.f32 "
                 "{%0,%1,%2,%3}, {%4,%5}, {%6}, {%0,%1,%2,%3};"
                 : "+f"(d[0]), "+f"(d[1]), "+f"(d[2]), "+f"(d[3])
                 : "r"(a0), "r"(a1), "r"(b0));
}
__device__ __forceinline__ void ldsm_x4(uint32_t& r0, uint32_t& r1, uint32_t& r2, uint32_t& r3,
                                        uint32_t addr) {
    asm volatile("ldmatrix.sync.aligned.m8n8.x4.shared.b16 {%0,%1,%2,%3}, [%4];"
                 : "=r"(r0), "=r"(r1), "=r"(r2), "=r"(r3) : "r"(addr));
}
#define CP_A16(dst, src) \
    asm volatile("cp.async.cg.shared.global [%0], [%1], 16;" :: "r"(dst), "l"(src) : "memory")
#define CP_COMMIT() asm volatile("cp.async.commit_group;" ::: "memory")
#define CP_WAIT(n)  asm volatile("cp.async.wait_group %0;" :: "n"(n) : "memory")

__device__ __forceinline__ void h_split(float x, __half& hi, __half& lo) {
    hi = __float2half_rn(x);
    lo = __float2half_rn(x - __half2float(hi));
}
__device__ __forceinline__ uint32_t hmul2(uint32_t a, uint32_t b) {
    uint32_t r;
    asm("mul.rn.f16x2 %0, %1, %2;" : "=r"(r) : "r"(a), "r"(b));
    return r;
}

// ---------------------------------------------------------------------------
// Kernel 1: Q/K/V projections (Q,K fp16; K row gets baked const channels).
// Block NB: dirfold + flag reset.  Block NB+1: W1T fp16 transpose.
// ---------------------------------------------------------------------------
#define QKV_ROWS 16
#define QKV_NB   (BB*NN/QKV_ROWS)
#define QKV_SMEM (3*HH*HH*4 + QKV_ROWS*HH*4)
__global__ void __launch_bounds__(512, 2)
qkv_kernel(const float* __restrict__ feat, const float* __restrict__ loc,
           const float* __restrict__ Wq, const float* __restrict__ bq,
           const float* __restrict__ Wk, const float* __restrict__ bk,
           const float* __restrict__ Wv, const float* __restrict__ bv,
           const float* __restrict__ Wd, const float* __restrict__ bd,
           const float* __restrict__ W1, const float* __restrict__ b1) {
    const int t = threadIdx.x;

    if (blockIdx.x == QKV_NB) {
        // ---- flag reset (graph-replay determinism)
        if (t >= MLPD && t < MLPD + BB*NN/8) g_flag[t - MLPD] = 0;
        // ---- dirfold: E = Wd @ W1[64:], c0 = b1 + bd @ W1[64:]
        if (t < MLPD) {
            int m = t;
            float e0 = 0.f, e1 = 0.f, e2 = 0.f, e3 = 0.f, c = b1[m];
#pragma unroll 16
            for (int d = 0; d < DIRD; ++d) {
                float w = W1[(HH + d)*MLPD + m];
                e0 = fmaf(Wd[0*DIRD + d], w, e0);
                e1 = fmaf(Wd[1*DIRD + d], w, e1);
                e2 = fmaf(Wd[2*DIRD + d], w, e2);
                e3 = fmaf(Wd[3*DIRD + d], w, e3);
                c  = fmaf(bd[d],          w, c);
            }
            g_E[0*MLPD + m] = e0;
            g_E[1*MLPD + m] = e1;
            g_E[2*MLPD + m] = e2;
            g_E[3*MLPD + m] = e3;
            g_c0[m] = c;
        }
        return;
    }
    if (blockIdx.x == QKV_NB + 1) {
        // ---- W1T fp16: g_W1Th[m*64 + h] = f16(W1[h*128 + m])
#pragma unroll
        for (int k = 0; k < 16; ++k) {
            int idx = t + k*512;
            int m = idx >> 6, h = idx & 63;
            g_W1Th[idx] = __float2half_rn(W1[h*MLPD + m]);
        }
        return;
    }

    extern __shared__ float qs[];
    float* sWq = qs;
    float* sWk = qs + HH*HH;
    float* sWv = qs + 2*HH*HH;
    float* sF  = qs + 3*HH*HH;
    const int row0 = blockIdx.x * QKV_ROWS;

    {
        const float4* wq4 = (const float4*)Wq;
        const float4* wk4 = (const float4*)Wk;
        const float4* wv4 = (const float4*)Wv;
        float4* dq = (float4*)sWq;
        float4* dk = (float4*)sWk;
        float4* dv = (float4*)sWv;
#pragma unroll
        for (int k = 0; k < 2; ++k) {
            int idx = t + k*512;
            dq[idx] = wq4[idx];
            dk[idx] = wk4[idx];
            dv[idx] = wv4[idx];
        }
        const float4* f4 = (const float4*)&feat[row0*HH];
        if (t < QKV_ROWS*HH/4) ((float4*)sF)[t] = f4[t];
    }
    __syncthreads();

    const int h = t & 63;
    const int rg = t >> 6;               // 8 groups x 2 rows
    float aq[2], ak[2], av[2];
    float vbq = bq[h], vbk = bk[h], vbv = bv[h];
#pragma unroll
    for (int r = 0; r < 2; ++r) { aq[r] = vbq; ak[r] = vbk; av[r] = vbv; }
#pragma unroll 8
    for (int k = 0; k < HH; ++k) {
        float wq = sWq[k*HH + h], wk = sWk[k*HH + h], wv = sWv[k*HH + h];
#pragma unroll
        for (int r = 0; r < 2; ++r) {
            float f = sF[(rg*2 + r)*HH + k];
            aq[r] = fmaf(f, wq, aq[r]);
            ak[r] = fmaf(f, wk, ak[r]);
            av[r] = fmaf(f, wv, av[r]);
        }
    }
#pragma unroll
    for (int r = 0; r < 2; ++r) {
        int row = row0 + rg*2 + r;
        g_Qh[row*HH + h]   = __float2half_rn(aq[r]);
        g_KhX[row*LDH + h] = __float2half_rn(ak[r]);
        g_V[row*HH + h]    = av[r];
    }
    // baked A const channels (k = 64..71) for this block's rows
    if (t < QKV_ROWS) {
        int row = row0 + t;
        int j = row & (NN - 1);
        float2 l = *(const float2*)&loc[j*2];
        __half l0h, l0l, l1h, l1l;
        h_split(l.x, l0h, l0l);
        h_split(l.y, l1h, l1l);
        __half one = __float2half_rn(1.f);
        __half c[8] = {one, one, l0h, l0h, l0l, l1h, l1h, l1l};
        *(uint4*)&g_KhX[row*LDH + 64] = *(uint4*)c;
    }
}

// ---------------------------------------------------------------------------
// Kernel 2 (fused): blocks < 2048 -> scores for (b,i) + publish flag.
// blocks >= 2048 -> softmax + attn@V for one 8-row group (spin on flags).
// Producer: TWO j-passes of 256 rows (small sA), 3 CTAs/SM for latency cover.
// ---------------------------------------------------------------------------
#define SA_OFF   0                   // 256*72*2 = 36864
#define SB_OFF   36864               // 128*72*2 = 18432 -> 55296
#define SP_OFF   55296               // 4*256*4  = 4096  -> 59392
#define SW2_OFF  59392               // 128*4    = 512   -> 59904
#define SC_TOTAL 59904
#define IB 8
#define VT 64
#define NSCORE (BB*NN)

__global__ void __launch_bounds__(256, 3)
attn_fused_kernel(const float* __restrict__ wind, const float* __restrict__ loc,
                  const float* __restrict__ W2, float* __restrict__ out) {
    extern __shared__ __align__(16) char sm[];
    const int t    = threadIdx.x;
    const int wid  = t >> 5;
    const int lane = t & 31;
    const int blk  = blockIdx.x;

    if (blk >= NSCORE) {
        // =============== consumer: softmax + attn@V for one group ===========
        float* sS = (float*)sm;               // [IB][NN]
        float* sV = (float*)(sm + IB*NN*4);   // [2][VT][HH]
        const int grp = blk - NSCORE;         // 0..255
        const int b   = grp >> 6;
        const int i0  = (grp & 63) * IB;
        const int bN  = b * NN;
        const uint32_t svb = smem_u32(sV);

        // prefetch V tile 0 (V ready: qkv retired before this kernel)
        {
            const char* src = (const char*)&g_V[bN*HH];
#pragma unroll
            for (int k = 0; k < 4; ++k) {
                int idx = t + k*256;
                CP_A16(svb + idx*16, src + idx*16);
            }
            CP_COMMIT();
        }

        // spin until this group's 8 producer blocks have published
        if (t == 0) {
            int v;
            do {
                asm volatile("ld.acquire.gpu.s32 %0, [%1];"
                             : "=r"(v) : "l"(&g_flag[grp]) : "memory");
                if (v != IB) __nanosleep(128);
            } while (v != IB);
        }
        __syncthreads();
        __threadfence();

        // load 8 rows of raw scores
        {
            const float4* src = (const float4*)&g_S[((size_t)bN + i0) * NN];
            float4* dst = (float4*)sS;
#pragma unroll
            for (int k = 0; k < 4; ++k) dst[t + k*256] = src[t + k*256];
        }
        __syncthreads();

        // per-row softmax: warp wid owns row wid
        float inv;
        {
            float* r = &sS[wid*NN];
            float m = -1e30f;
#pragma unroll
            for (int c = 0; c < NN/32; ++c) m = fmaxf(m, r[c*32 + lane]);
#pragma unroll
            for (int o = 16; o > 0; o >>= 1) m = fmaxf(m, __shfl_xor_sync(0xffffffffu, m, o));
            float sum = 0.f;
#pragma unroll
            for (int c = 0; c < NN/32; ++c) {
                float e = __expf(r[c*32 + lane] - m);
                r[c*32 + lane] = e;
                sum += e;
            }
#pragma unroll
            for (int o = 16; o > 0; o >>= 1) sum += __shfl_xor_sync(0xffffffffu, sum, o);
            inv = 1.f / sum;
        }

        // AV over 8 V tiles (double-buffered)
        const int h4 = lane & 15;
        const int jh = lane >> 4;
        float4 acc = make_float4(0.f, 0.f, 0.f, 0.f);

#pragma unroll
        for (int jt = 0; jt < NN/VT; ++jt) {
            if (jt + 1 < NN/VT) {
                const char* src = (const char*)&g_V[(bN + (jt + 1)*VT)*HH];
                uint32_t dstb = svb + ((jt + 1) & 1) * (VT*HH*4);
#pragma unroll
                for (int k = 0; k < 4; ++k) {
                    int idx = t + k*256;
                    CP_A16(dstb + idx*16, src + idx*16);
                }
                CP_COMMIT();
                CP_WAIT(1);
            } else {
                CP_WAIT(0);
            }
            __syncthreads();
            const float*  Prow = &sS[wid*NN + jt*VT + jh*32];
            const float4* V4   = (const float4*)&sV[(jt & 1)*VT*HH];
#pragma unroll 4
            for (int j = 0; j < 32; ++j) {
                float p = Prow[j];
                float4 v = V4[(jh*32 + j)*16 + h4];
                acc.x = fmaf(p, v.x, acc.x);
                acc.y = fmaf(p, v.y, acc.y);
                acc.z = fmaf(p, v.z, acc.z);
                acc.w = fmaf(p, v.w, acc.w);
            }
            __syncthreads();
        }

        acc.x += __shfl_xor_sync(0xffffffffu, acc.x, 16);
        acc.y += __shfl_xor_sync(0xffffffffu, acc.y, 16);
        acc.z += __shfl_xor_sync(0xffffffffu, acc.z, 16);
        acc.w += __shfl_xor_sync(0xffffffffu, acc.w, 16);
        if (jh == 0) {
            acc.x *= inv; acc.y *= inv; acc.z *= inv; acc.w *= inv;
            ((float4*)&out[(bN + i0 + wid)*HH])[h4] = acc;
        }
        return;
    }

    // =================== producer: scores for (b,i) ========================
    __half*  sA  = (__half*)(sm + SA_OFF);
    __half*  sB  = (__half*)(sm + SB_OFF);
    float*   sP  = (float*)(sm + SP_OFF);
    float*   sW2 = (float*)(sm + SW2_OFF);

    const int b    = blk >> 9;
    const int i    = blk & (NN - 1);
    const int bN   = b * NN;
    const uint32_t sAb = smem_u32(sA);
    const uint32_t sBb = smem_u32(sB);

    // 1. cp.async A pass-0 (rows 0..255, data + baked const channels)
    {
        const char* src = (const char*)&g_KhX[bN*LDH];
#pragma unroll
        for (int k = 0; k < 9; ++k) {
            uint32_t off = (uint32_t)(t + k*256) * 16;
            CP_A16(sAb + off, src + off);
        }
        CP_COMMIT();
    }

    // 2. per-i constant channels for B rows (k = 64..71) + W2
    if (t < MLPD) {
        float li0 = loc[i*2 + 0], li1 = loc[i*2 + 1];
        float w0  = wind[(bN + i)*2 + 0], w1v = wind[(bN + i)*2 + 1];
        float e0 = g_E[t], e1 = g_E[MLPD + t], e2 = g_E[2*MLPD + t], e3 = g_E[3*MLPD + t];
        float f  = g_c0[t] - li0*e0 - li1*e1 + w0*e2 + w1v*e3;
        __half fh, fl, e0h, e0l, e1h, e1l;
        h_split(f,  fh,  fl);
        h_split(e0, e0h, e0l);
        h_split(e1, e1h, e1l);
        __half c[8] = {fh, fl, e0h, e0l, e0h, e1h, e1l, e1h};
        *(uint4*)&sB[t*LDH + 64] = *(uint4*)c;
        sW2[t] = W2[t];
    }

    // 3. stage B data: sB[m][h] = W1Th[m][h] * Qh[i][h]  (fp16 x fp16)
    {
        const uint4* w4 = (const uint4*)g_W1Th;
        const uint4* q4 = (const uint4*)&g_Qh[(bN + i)*HH];
#pragma unroll
        for (int k = 0; k < 4; ++k) {
            int idx = t + k*256;
            int m = idx >> 3, oct = idx & 7;
            uint4 w = __ldg(&w4[idx]);
            uint4 q = __ldg(&q4[oct]);
            uint4 r;
            r.x = hmul2(w.x, q.x);
            r.y = hmul2(w.y, q.y);
            r.z = hmul2(w.z, q.z);
            r.w = hmul2(w.w, q.w);
            *(uint4*)&sB[m*LDH + oct*8] = r;
        }
    }
    CP_WAIT(0);
    __syncthreads();   // A pass-0 + B fully staged

    const int wj  = wid >> 2;      // 0..1  (j half of pass: 128 rows)
    const int wm  = wid & 3;       // 0..3  (m block of 32)
    const int g   = lane >> 2;
    const int tig = lane & 3;

    // hoisted B fragments: all 4 kc chunks (invariant across subtiles/passes)
    uint32_t Bf[4][4][2];
    {
        int idx4   = lane >> 3;
        int ni_off = idx4 >> 1;
        int koff   = (idx4 & 1) * 8;
        int n0 = wm*32 + 0*16 + ni_off*8 + (lane & 7);
        int n1 = wm*32 + 1*16 + ni_off*8 + (lane & 7);
        uint32_t bAddr0 = sBb + (uint32_t)(n0*LDH + koff) * 2;
        uint32_t bAddr1 = sBb + (uint32_t)(n1*LDH + koff) * 2;
#pragma unroll
        for (int kc = 0; kc < 4; ++kc) {
            const uint32_t kb = kc * 32;
            ldsm_x4(Bf[kc][0][0], Bf[kc][0][1], Bf[kc][1][0], Bf[kc][1][1], bAddr0 + kb);
            ldsm_x4(Bf[kc][2][0], Bf[kc][2][1], Bf[kc][3][0], Bf[kc][3][1], bAddr1 + kb);
        }
    }
    // hoisted B k8 fragments
    uint32_t B8[4];
    {
        int n = wm*32 + (lane >> 3)*8 + (lane & 7);
        ldsm_x4(B8[0], B8[1], B8[2], B8[3], sBb + (uint32_t)(n*LDH + 64) * 2);
    }
    // hoisted W2 registers
    float w2r[8];
#pragma unroll
    for (int ni = 0; ni < 4; ++ni) {
        int m0 = wm*32 + ni*8 + 2*tig;
        w2r[ni*2]     = sW2[m0];
        w2r[ni*2 + 1] = sW2[m0 + 1];
    }

    // per-lane A address components (pass/subtile-invariant)
    const int aRowLoc  = lane & 15;
    const int aKOff    = (lane >> 4) * 8;
    const int a8RowLoc = ((lane >> 4) & 1)*16 + (((lane >> 3) & 1))*8 + (lane & 7);

#pragma unroll
    for (int p = 0; p < 2; ++p) {
        // 4. compute pass p: 4 subtiles of 32 j-rows per warp (rows 0..255 of sA)
#pragma unroll
        for (int tj = 0; tj < 4; ++tj) {
            const int rowb = wj*128 + tj*32;
            uint32_t aAddr[2];
#pragma unroll
            for (int mi = 0; mi < 2; ++mi) {
                int r0 = rowb + mi*16 + aRowLoc;
                aAddr[mi] = sAb + (uint32_t)(r0*LDH + aKOff) * 2;
            }
            uint32_t a8Addr = sAb + (uint32_t)((rowb + a8RowLoc)*LDH + 64) * 2;

            float d[2][4][4];
#pragma unroll
            for (int mi = 0; mi < 2; ++mi)
#pragma unroll
                for (int ni = 0; ni < 4; ++ni)
#pragma unroll
                    for (int r = 0; r < 4; ++r) d[mi][ni][r] = 0.f;

            // constant-channel k8 MMAs
            {
                uint32_t A8[4];
                ldsm_x4(A8[0], A8[1], A8[2], A8[3], a8Addr);
#pragma unroll
                for (int mi = 0; mi < 2; ++mi)
#pragma unroll
                    for (int ni = 0; ni < 4; ++ni)
                        mma_f16_k8(d[mi][ni], A8[mi*2], A8[mi*2 + 1], B8[ni]);
            }

#pragma unroll
            for (int kc = 0; kc < 4; ++kc) {
                const uint32_t kb = kc * 32;
                uint32_t Af[2][4];
#pragma unroll
                for (int mi = 0; mi < 2; ++mi)
                    ldsm_x4(Af[mi][0], Af[mi][1], Af[mi][2], Af[mi][3], aAddr[mi] + kb);
#pragma unroll
                for (int mi = 0; mi < 2; ++mi)
#pragma unroll
                    for (int ni = 0; ni < 4; ++ni)
                        mma_f16(d[mi][ni], Af[mi], Bf[kc][ni]);
            }

            // lean epilogue: relu . W2 only
#pragma unroll
            for (int mi = 0; mi < 2; ++mi) {
                int jl = rowb + mi*16 + g;
                float p0 = 0.f, p1 = 0.f;
#pragma unroll
                for (int ni = 0; ni < 4; ++ni) {
                    p0 = fmaf(fmaxf(d[mi][ni][0], 0.f), w2r[ni*2],     p0);
                    p0 = fmaf(fmaxf(d[mi][ni][1], 0.f), w2r[ni*2 + 1], p0);
                    p1 = fmaf(fmaxf(d[mi][ni][2], 0.f), w2r[ni*2],     p1);
                    p1 = fmaf(fmaxf(d[mi][ni][3], 0.f), w2r[ni*2 + 1], p1);
                }
                p0 += __shfl_xor_sync(0xffffffffu, p0, 1);
                p0 += __shfl_xor_sync(0xffffffffu, p0, 2);
                p1 += __shfl_xor_sync(0xffffffffu, p1, 1);
                p1 += __shfl_xor_sync(0xffffffffu, p1, 2);
                if (tig == 0) {
                    sP[wm*256 + jl]     = p0;
                    sP[wm*256 + jl + 8] = p1;
                }
            }
        }
        __syncthreads();   // all sA reads + sP writes for pass p done

        // 5. kick A restage for pass 1 (overlaps the combine below)
        if (p == 0) {
            const char* src = (const char*)&g_KhX[(bN + 256)*LDH];
#pragma unroll
            for (int k = 0; k < 9; ++k) {
                uint32_t off = (uint32_t)(t + k*256) * 16;
                CP_A16(sAb + off, src + off);
            }
            CP_COMMIT();
        }

        // 6. combine 4 m-block partials, write raw scores for this pass
        {
            float s = sP[t] + sP[256 + t] + sP[512 + t] + sP[768 + t];
            g_S[(size_t)blk*NN + p*256 + t] = s;
        }

        if (p == 0) {
            CP_WAIT(0);
            __syncthreads();   // pass-1 A staged; sP reads done before rewrite
        }
    }
    __syncthreads();
    if (t == 0) {
        __threadfence();
        atomicAdd(&g_flag[blk >> 3], 1);
    }
}

// ---------------------------------------------------------------------------
extern "C" void kernel_launch(void* const* d_in, const int* in_sizes, int n_in,
                              void* d_out, int out_size) {
    const float* features = (const float*)d_in[0];
    const float* wind     = (const float*)d_in[1];
    const float* loc      = (const float*)d_in[2];
    const float* Wq       = (const float*)d_in[3];
    const float* bq       = (const float*)d_in[4];
    const float* Wk       = (const float*)d_in[5];
    const float* bk       = (const float*)d_in[6];
    const float* Wv       = (const float*)d_in[7];
    const float* bv       = (const float*)d_in[8];
    const float* Wd       = (const float*)d_in[9];
    const float* bd       = (const float*)d_in[10];
    const float* W1       = (const float*)d_in[11];
    const float* b1       = (const float*)d_in[12];
    const float* W2       = (const float*)d_in[13];
    // d_in[14] = b2: softmax-invariant -> dropped.
    (void)in_sizes; (void)n_in; (void)out_size;

    cudaFuncSetAttribute(qkv_kernel, cudaFuncAttributeMaxDynamicSharedMemorySize, QKV_SMEM);
    cudaFuncSetAttribute(attn_fused_kernel, cudaFuncAttributeMaxDynamicSharedMemorySize, SC_TOTAL);

    qkv_kernel<<<QKV_NB + 2, 512, QKV_SMEM>>>(features, loc, Wq, bq, Wk, bk, Wv, bv,
                                              Wd, bd, W1, b1);
    attn_fused_kernel<<<NSCORE + NSCORE/IB, 256, SC_TOTAL>>>(wind, loc, W2, (float*)d_out);
}